// round 11
// baseline (speedup 1.0000x reference)
#include <cuda_runtime.h>
#include <cuda_bf16.h>
#include <stdint.h>
#include <math.h>

// Problem constants
#define BB 2
#define TT 2048
#define DD 1024
#define NH 16
#define HDIM 64
#define M_ROWS (BB*TT)          // 4096
#define N_QKV (3*DD)            // 3072
#define K3 (3*DD)               // split-K' = 3*1024
#define BH (BB*NH)              // 32

// ---------------- scratch (static device globals: allocation-free) ----------
__device__ float g_qkv[M_ROWS * N_QKV];                    // 4096 x 3072 fp32
__device__ float g_att[M_ROWS * DD];
__device__ __nv_bfloat16 g_a3 [M_ROWS * K3];               // [M, 3K] split A (reused)
__device__ __nv_bfloat16 g_bq3[N_QKV * K3];                // [N, 3K] split W_qkv^T
__device__ __nv_bfloat16 g_bo3[DD * K3];                   // [N, 3K] split W_out^T
__device__ __nv_bfloat16 g_q3 [BH * TT * 192];             // [bh][t][192] split Q (scaled)
__device__ __nv_bfloat16 g_k3 [BH * TT * 192];             // [bh][t][192] split K
__device__ __nv_bfloat16 g_vth[BH * HDIM * TT];            // [bh][d][t] V hi (transposed)
__device__ __nv_bfloat16 g_vtl[BH * HDIM * TT];            // [bh][d][t] V lo

// ======================= PTX helpers =========================================
__device__ __forceinline__ uint32_t smem_u32(const void* p) {
    uint32_t a;
    asm("{ .reg .u64 t; cvta.to.shared.u64 t, %1; cvt.u32.u64 %0, t; }"
        : "=r"(a) : "l"(p));
    return a;
}
#define CP_ASYNC16(dst, src) \
    asm volatile("cp.async.cg.shared.global [%0], [%1], 16;" \
                 :: "r"(dst), "l"(src) : "memory")
#define CP_COMMIT() asm volatile("cp.async.commit_group;" ::: "memory")
#define CP_WAIT1()  asm volatile("cp.async.wait_group 1;" ::: "memory")
#define CP_WAIT0()  asm volatile("cp.async.wait_group 0;" ::: "memory")

__device__ __forceinline__ void ldm_x4(uint32_t* r, uint32_t a) {
    asm volatile("ldmatrix.sync.aligned.m8n8.x4.shared.b16 {%0,%1,%2,%3}, [%4];"
                 : "=r"(r[0]), "=r"(r[1]), "=r"(r[2]), "=r"(r[3]) : "r"(a));
}
__device__ __forceinline__ void mma16816(float* c, const uint32_t* a,
                                         const uint32_t* b) {
    asm volatile(
        "mma.sync.aligned.m16n8k16.row.col.f32.bf16.bf16.f32 "
        "{%0,%1,%2,%3}, {%4,%5,%6,%7}, {%8,%9}, {%0,%1,%2,%3};"
        : "+f"(c[0]), "+f"(c[1]), "+f"(c[2]), "+f"(c[3])
        : "r"(a[0]), "r"(a[1]), "r"(a[2]), "r"(a[3]), "r"(b[0]), "r"(b[1]));
}
// pack {lo=trunc_bf16(a), hi=trunc_bf16(b)} in one PRMT
__device__ __forceinline__ uint32_t prmt_hi16(float a, float b) {
    uint32_t r;
    asm("prmt.b32 %0, %1, %2, 0x7632;"
        : "=r"(r) : "r"(__float_as_uint(a)), "r"(__float_as_uint(b)));
    return r;
}
__device__ __forceinline__ uint32_t pack_bf16(float lo, float hi) {
    uint32_t r;
    asm("cvt.rn.bf16x2.f32 %0, %1, %2;" : "=r"(r) : "f"(hi), "f"(lo));
    return r;
}
__device__ __forceinline__ float trunc_bf(float a) {
    return __uint_as_float(__float_as_uint(a) & 0xFFFF0000u);
}
// fast 2^t for t <= 0 on FMA/ALU pipes (no MUFU). |rel err| ~2e-6.
__device__ __forceinline__ float exp2p(float t) {
    t = fmaxf(t, -30.f);
    float fm = t + 12582912.f;                       // round-to-nearest int
    int n = __float_as_int(fm) - 0x4B400000;
    float f = t - (fm - 12582912.f);                 // [-0.5, 0.5]
    float p = 0.0013333558f;
    p = fmaf(p, f, 0.0096181291f);
    p = fmaf(p, f, 0.0555041087f);
    p = fmaf(p, f, 0.2402265069f);
    p = fmaf(p, f, 0.6931471806f);
    p = fmaf(p, f, 1.0f);
    return p * __int_as_float((n + 127) << 23);
}

// ======================= split / transpose kernels ===========================
__global__ __launch_bounds__(256) void split_a(
    const float* __restrict__ A, __nv_bfloat16* __restrict__ A3, int total)
{
    int idx = blockIdx.x * blockDim.x + threadIdx.x;
    if (idx >= total) return;
    int m = idx / DD, k = idx - m * DD;
    float a = A[idx];
    __nv_bfloat16 hi = __float2bfloat16(a);
    __nv_bfloat16 lo = __float2bfloat16(a - __bfloat162float(hi));
    size_t rb = (size_t)m * K3;
    A3[rb + k] = hi;
    A3[rb + DD + k] = hi;
    A3[rb + 2 * DD + k] = lo;
}

__global__ __launch_bounds__(256) void split_bt(
    const float* __restrict__ W, __nv_bfloat16* __restrict__ Bt3, int N)
{
    __shared__ float tile[32][33];
    int n0 = blockIdx.x * 32;
    int k0 = blockIdx.y * 32;
    int tx = threadIdx.x & 31;
    int ty = threadIdx.x >> 5;
    for (int r = ty; r < 32; r += 8)
        tile[r][tx] = W[(size_t)(k0 + r) * N + n0 + tx];
    __syncthreads();
    for (int r = ty; r < 32; r += 8) {
        int n = n0 + r;
        int k = k0 + tx;
        float w = tile[tx][r];
        __nv_bfloat16 hi = __float2bfloat16(w);
        __nv_bfloat16 lo = __float2bfloat16(w - __bfloat162float(hi));
        size_t rb = (size_t)n * K3;
        Bt3[rb + k] = hi;
        Bt3[rb + DD + k] = lo;
        Bt3[rb + 2 * DD + k] = hi;
    }
}

// ======================= mma.sync GEMM (3-stage, 1 barrier/chunk) ============
#define SM_STRIDE 40
#define G_STAGE (2 * 128 * SM_STRIDE * 2)       // A+B per stage = 20480 B
#define G_AB (128 * SM_STRIDE * 2)              // 10240 B
#define GEMM_SMEM_MMA (3 * G_STAGE)             // 61440 B

__global__ __launch_bounds__(256, 2) void gemm_mma(
    const __nv_bfloat16* __restrict__ A, const __nv_bfloat16* __restrict__ Bt,
    const float* __restrict__ bias, float* __restrict__ C, int N)
{
    extern __shared__ char smem[];

    const int tid = threadIdx.x;
    const int lane = tid & 31;
    const int wid = tid >> 5;
    const int wm = wid >> 2;
    const int wn = wid & 3;
    const int bm = blockIdx.y;
    const int bn = blockIdx.x;
    const int KCH = K3 / 32;                    // 96

    const uint32_t shA0 = smem_u32(smem);

    const int prow = tid >> 2;
    const int pseg = (tid & 3) * 8;
    const size_t arow0 = (size_t)(bm * 128 + prow) * K3 + pseg;
    const size_t brow0 = (size_t)(bn * 128 + prow) * K3 + pseg;
    const size_t arow1 = (size_t)(bm * 128 + prow + 64) * K3 + pseg;
    const size_t brow1 = (size_t)(bn * 128 + prow + 64) * K3 + pseg;
    const uint32_t dA0 = (prow * SM_STRIDE + pseg) * 2;
    const uint32_t dA1 = ((prow + 64) * SM_STRIDE + pseg) * 2;

    float c[4][4][4];
#pragma unroll
    for (int i = 0; i < 4; i++)
#pragma unroll
        for (int j = 0; j < 4; j++)
#pragma unroll
            for (int r = 0; r < 4; r++) c[i][j][r] = 0.f;

    const int lr = lane & 7;
    const int sel = lane >> 3;
    const uint32_t aRow = wm * 64 + lr + ((sel & 1) << 3);
    const uint32_t aCol = (sel >> 1) << 3;
    const uint32_t aOff = (aRow * SM_STRIDE + aCol) * 2;
    const uint32_t bRow = wn * 32 + lr + ((sel >> 1) << 3);
    const uint32_t bCol = (sel & 1) << 3;
    const uint32_t bOff = (bRow * SM_STRIDE + bCol) * 2;

    auto issue = [&](int chunk) {
        uint32_t sb = shA0 + (uint32_t)(chunk % 3) * G_STAGE;
        size_t ko = (size_t)chunk * 32;
        CP_ASYNC16(sb + dA0, A + arow0 + ko);
        CP_ASYNC16(sb + G_AB + dA0, Bt + brow0 + ko);
        CP_ASYNC16(sb + dA1, A + arow1 + ko);
        CP_ASYNC16(sb + G_AB + dA1, Bt + brow1 + ko);
    };

    issue(0); CP_COMMIT();
    issue(1); CP_COMMIT();

    for (int kc = 0; kc < KCH; kc++) {
        if (kc + 1 < KCH) CP_WAIT1(); else CP_WAIT0();
        __syncthreads();
        if (kc + 2 < KCH) { issue(kc + 2); CP_COMMIT(); }

        uint32_t sb = shA0 + (uint32_t)(kc % 3) * G_STAGE;
#pragma unroll
        for (int ks = 0; ks < 2; ks++) {
            uint32_t af[4][4], bf[4][2];
#pragma unroll
            for (int mi = 0; mi < 4; mi++)
                ldm_x4(af[mi], sb + aOff + (mi * 16 * SM_STRIDE + ks * 16) * 2);
#pragma unroll
            for (int p = 0; p < 2; p++) {
                uint32_t r4[4];
                ldm_x4(r4, sb + G_AB + bOff +
                           (p * 16 * SM_STRIDE + ks * 16) * 2);
                bf[p * 2][0] = r4[0]; bf[p * 2][1] = r4[1];
                bf[p * 2 + 1][0] = r4[2]; bf[p * 2 + 1][1] = r4[3];
            }
#pragma unroll
            for (int mi = 0; mi < 4; mi++)
#pragma unroll
                for (int nj = 0; nj < 4; nj++)
                    mma16816(c[mi][nj], af[mi], bf[nj]);
        }
    }

    const int cn0 = bn * 128 + wn * 32 + (lane & 3) * 2;
    const int cm0 = bm * 128 + wm * 64 + (lane >> 2);
#pragma unroll
    for (int nj = 0; nj < 4; nj++) {
        int col = cn0 + nj * 8;
        float bv0 = bias[col], bv1 = bias[col + 1];
#pragma unroll
        for (int mi = 0; mi < 4; mi++) {
            int row = cm0 + mi * 16;
            float2 v0 = make_float2(c[mi][nj][0] + bv0, c[mi][nj][1] + bv1);
            float2 v1 = make_float2(c[mi][nj][2] + bv0, c[mi][nj][3] + bv1);
            *(float2*)(C + (size_t)row * N + col) = v0;
            *(float2*)(C + (size_t)(row + 8) * N + col) = v1;
        }
    }
}

// ---------------- RoPE -> split Q3/K3 ([bh][t][192] bf16) -------------------
// Q3 windows: [hi | hi | lo] (scaled by 0.125*log2(e));  K3: [hi | lo | hi].
__global__ __launch_bounds__(256) void rope_split2(
    const float* __restrict__ qkv,
    __nv_bfloat16* __restrict__ Q3, __nv_bfloat16* __restrict__ K3g)
{
    int idx = blockIdx.x * blockDim.x + threadIdx.x;
    int i = idx & 31;
    int h = (idx >> 5) & (NH - 1);
    int t = (idx >> 9) & (TT - 1);
    int b = idx >> 20;

    const float* base = qkv + (size_t)(b * TT + t) * N_QKV;
    const float* qs = base + h * HDIM;
    const float* ks = base + DD + h * HDIM;

    float tf = (float)t;
    float sn, cs;
    if (i < 16) {
        float f1 = tf * powf(10000.f, -(float)(4 * i) / 64.f);
        float f2 = tf * powf(10000.f, -(float)(4 * i + 2) / 64.f);
        sn = sinf(f1);
        cs = sinf(f2);
    } else {
        float f1 = tf * powf(10000.f, -(float)(4 * i - 64) / 64.f);
        float f2 = tf * powf(10000.f, -(float)(4 * i - 62) / 64.f);
        sn = cosf(f1);
        cs = cosf(f2);
    }

    const float QSC = 0.125f * 1.44269504f;   // scale * log2(e), folded into Q
    size_t ob = ((size_t)(b * NH + h) * TT + t) * 192;

    float q1 = qs[2 * i], q2 = qs[2 * i + 1];
    float qa = (q1 * cs - q2 * sn) * QSC;     // dim i
    float qb = (q1 * sn + q2 * cs) * QSC;     // dim 32+i
    __nv_bfloat16 qah = __float2bfloat16(qa);
    __nv_bfloat16 qbh = __float2bfloat16(qb);
    Q3[ob + i]       = qah;  Q3[ob + 64 + i]  = qah;
    Q3[ob + 128 + i] = __float2bfloat16(qa - __bfloat162float(qah));
    Q3[ob + 32 + i]  = qbh;  Q3[ob + 96 + i]  = qbh;
    Q3[ob + 160 + i] = __float2bfloat16(qb - __bfloat162float(qbh));

    float k1 = ks[2 * i], k2 = ks[2 * i + 1];
    float ka = k1 * cs - k2 * sn;
    float kb = k1 * sn + k2 * cs;
    __nv_bfloat16 kah = __float2bfloat16(ka);
    __nv_bfloat16 kbh = __float2bfloat16(kb);
    K3g[ob + i]       = kah;
    K3g[ob + 64 + i]  = __float2bfloat16(ka - __bfloat162float(kah));
    K3g[ob + 128 + i] = kah;
    K3g[ob + 32 + i]  = kbh;
    K3g[ob + 96 + i]  = __float2bfloat16(kb - __bfloat162float(kbh));
    K3g[ob + 160 + i] = kbh;
}

// ---------------- V transpose + hi/lo split: [bh][d][t] ---------------------
__global__ __launch_bounds__(256) void vsplit_t(
    const float* __restrict__ qkv,
    __nv_bfloat16* __restrict__ Vh, __nv_bfloat16* __restrict__ Vl)
{
    __shared__ float tile[32][33];
    int t0 = blockIdx.x * 32;
    int d0 = blockIdx.y * 32;
    int bh = blockIdx.z;
    int b = bh >> 4, h = bh & 15;
    int tx = threadIdx.x & 31;
    int ty = threadIdx.x >> 5;
    const float* src = qkv + ((size_t)(b * TT) + t0) * N_QKV + 2 * DD + h * HDIM + d0;
    for (int r = ty; r < 32; r += 8)
        tile[r][tx] = src[(size_t)r * N_QKV + tx];
    __syncthreads();
    for (int r = ty; r < 32; r += 8) {
        float v = tile[tx][r];                   // t = t0+tx, d = d0+r
        __nv_bfloat16 hi = __float2bfloat16(v);
        size_t o = ((size_t)bh * HDIM + d0 + r) * TT + t0 + tx;
        Vh[o] = hi;
        Vl[o] = __float2bfloat16(v - __bfloat162float(hi));
    }
}

// ======================= mma.sync flash attention ============================
// Block = 128 q rows of one (b,h); 8 warps, m16 each; KV tiles of 64.
#define QSTR 200                 // padded bf16 stride (conflict-free ldmatrix)
#define KSTR 200
#define VSTR 72
#define ATT_STG 44032            // K 25600 + Vh 9216 + Vl 9216
#define ATT_SMEM (2 * ATT_STG)   // 88064

__global__ __launch_bounds__(256, 1) void attn_mma(
    const __nv_bfloat16* __restrict__ Q3, const __nv_bfloat16* __restrict__ K3g,
    const __nv_bfloat16* __restrict__ Vh, const __nv_bfloat16* __restrict__ Vl,
    float* __restrict__ O)
{
    extern __shared__ char smem[];
    const uint32_t su = smem_u32(smem);
    const int tid = threadIdx.x;
    const int lane = tid & 31;
    const int wm = tid >> 5;        // warp = 16 q rows
    const int qt = blockIdx.x;
    const int bh = blockIdx.y;
    const int q0 = qt * 128;
    const int jmax = 2 * qt + 2;

    const __nv_bfloat16* Qg  = Q3  + (size_t)bh * TT * 192;
    const __nv_bfloat16* Kg  = K3g + (size_t)bh * TT * 192;
    const __nv_bfloat16* Vhg = Vh  + (size_t)bh * HDIM * TT;
    const __nv_bfloat16* Vlg = Vl  + (size_t)bh * HDIM * TT;

    // ---- stage Q tile (128 x 192) and extract A-fragments, then free smem
#pragma unroll
    for (int c = 0; c < 12; c++) {
        int g = tid + 256 * c;
        int row = g / 24, seg = g % 24;
        CP_ASYNC16(su + row * (QSTR * 2) + seg * 16,
                   Qg + (size_t)(q0 + row) * 192 + seg * 8);
    }
    CP_COMMIT(); CP_WAIT0();
    __syncthreads();

    const int lr = lane & 7;
    const int sel = lane >> 3;
    uint32_t qf[12][4];
    {
        uint32_t ab = su + (wm * 16 + lr + ((sel & 1) << 3)) * (QSTR * 2)
                    + (((sel >> 1) << 3)) * 2;
#pragma unroll
        for (int kk = 0; kk < 12; kk++)
            ldm_x4(qf[kk], ab + kk * 32);
    }
    __syncthreads();

    float oacc[8][4];
#pragma unroll
    for (int i = 0; i < 8; i++)
#pragma unroll
        for (int j = 0; j < 4; j++) oacc[i][j] = 0.f;
    float mrow0 = -1e30f, mrow1 = -1e30f, lrow0 = 0.f, lrow1 = 0.f;

    auto issue = [&](int jt2) {
        int j0p = jt2 * 64;
        uint32_t sb = su + (jt2 & 1) * ATT_STG;
#pragma unroll
        for (int c = 0; c < 6; c++) {
            int g = tid + 256 * c;
            int row = g / 24, seg = g % 24;
            CP_ASYNC16(sb + row * (KSTR * 2) + seg * 16,
                       Kg + (size_t)(j0p + row) * 192 + seg * 8);
        }
#pragma unroll
        for (int c = 0; c < 2; c++) {
            int g = tid + 256 * c;
            int row = g >> 3, seg = g & 7;
            CP_ASYNC16(sb + 25600 + row * (VSTR * 2) + seg * 16,
                       Vhg + (size_t)row * TT + j0p + seg * 8);
            CP_ASYNC16(sb + 34816 + row * (VSTR * 2) + seg * 16,
                       Vlg + (size_t)row * TT + j0p + seg * 8);
        }
    };

    issue(0); CP_COMMIT();

    for (int jt = 0; jt < jmax; jt++) {
        if (jt + 1 < jmax) { issue(jt + 1); CP_COMMIT(); CP_WAIT1(); }
        else CP_WAIT0();
        __syncthreads();

        const int j0 = jt * 64;
        if (j0 <= q0 + wm * 16 + 15) {          // warp has unmasked work
            uint32_t sb = su + (jt & 1) * ATT_STG;

            // ---- S = Q K^T (n = kv cols 0..63)
            float sacc[8][4];
#pragma unroll
            for (int i = 0; i < 8; i++)
#pragma unroll
                for (int j = 0; j < 4; j++) sacc[i][j] = 0.f;

            uint32_t kb = sb + (lr + ((sel >> 1) << 3)) * (KSTR * 2)
                        + (((sel & 1) << 3)) * 2;
#pragma unroll
            for (int kk = 0; kk < 12; kk++) {
#pragma unroll
                for (int w = 0; w < 4; w++) {
                    uint32_t r4[4];
                    ldm_x4(r4, kb + (w * 16) * (KSTR * 2) + kk * 32);
                    mma16816(sacc[2 * w],     qf[kk], r4);
                    mma16816(sacc[2 * w + 1], qf[kk], r4 + 2);
                }
            }

            // ---- causal mask (diagonal region only)
            int r0 = q0 + wm * 16 + (lane >> 2);
            if (j0 + 63 > q0 + wm * 16) {
#pragma unroll
                for (int nt = 0; nt < 8; nt++) {
                    int cb = j0 + nt * 8 + (lane & 3) * 2;
                    if (cb     > r0)     sacc[nt][0] = -1e30f;
                    if (cb + 1 > r0)     sacc[nt][1] = -1e30f;
                    if (cb     > r0 + 8) sacc[nt][2] = -1e30f;
                    if (cb + 1 > r0 + 8) sacc[nt][3] = -1e30f;
                }
            }

            // ---- online softmax (base-2, poly exp on FMA pipe)
            float mx0 = -1e30f, mx1 = -1e30f;
#pragma unroll
            for (int nt = 0; nt < 8; nt++) {
                mx0 = fmaxf(mx0, fmaxf(sacc[nt][0], sacc[nt][1]));
                mx1 = fmaxf(mx1, fmaxf(sacc[nt][2], sacc[nt][3]));
            }
            mx0 = fmaxf(mx0, __shfl_xor_sync(0xffffffffu, mx0, 1));
            mx0 = fmaxf(mx0, __shfl_xor_sync(0xffffffffu, mx0, 2));
            mx1 = fmaxf(mx1, __shfl_xor_sync(0xffffffffu, mx1, 1));
            mx1 = fmaxf(mx1, __shfl_xor_sync(0xffffffffu, mx1, 2));
            float mn0 = fmaxf(mrow0, mx0), mn1 = fmaxf(mrow1, mx1);
            float a0 = exp2p(mrow0 - mn0), a1 = exp2p(mrow1 - mn1);
            mrow0 = mn0; mrow1 = mn1;
            lrow0 *= a0; lrow1 *= a1;
#pragma unroll
            for (int nt = 0; nt < 8; nt++) {
                oacc[nt][0] *= a0; oacc[nt][1] *= a0;
                oacc[nt][2] *= a1; oacc[nt][3] *= a1;
            }
            float rs0 = 0.f, rs1 = 0.f;
#pragma unroll
            for (int nt = 0; nt < 8; nt++) {
                sacc[nt][0] = exp2p(sacc[nt][0] - mn0);
                sacc[nt][1] = exp2p(sacc[nt][1] - mn0);
                sacc[nt][2] = exp2p(sacc[nt][2] - mn1);
                sacc[nt][3] = exp2p(sacc[nt][3] - mn1);
                rs0 += sacc[nt][0] + sacc[nt][1];
                rs1 += sacc[nt][2] + sacc[nt][3];
            }
            rs0 += __shfl_xor_sync(0xffffffffu, rs0, 1);
            rs0 += __shfl_xor_sync(0xffffffffu, rs0, 2);
            rs1 += __shfl_xor_sync(0xffffffffu, rs1, 1);
            rs1 += __shfl_xor_sync(0xffffffffu, rs1, 2);
            lrow0 += rs0; lrow1 += rs1;

            // ---- pack P hi (truncate) / lo into A-fragments
            uint32_t ah[4][4], al[4][4];
#pragma unroll
            for (int k2 = 0; k2 < 4; k2++) {
                float p00 = sacc[2 * k2][0],     p01 = sacc[2 * k2][1];
                float p02 = sacc[2 * k2][2],     p03 = sacc[2 * k2][3];
                float p10 = sacc[2 * k2 + 1][0], p11 = sacc[2 * k2 + 1][1];
                float p12 = sacc[2 * k2 + 1][2], p13 = sacc[2 * k2 + 1][3];
                ah[k2][0] = prmt_hi16(p00, p01);
                ah[k2][1] = prmt_hi16(p02, p03);
                ah[k2][2] = prmt_hi16(p10, p11);
                ah[k2][3] = prmt_hi16(p12, p13);
                al[k2][0] = pack_bf16(p00 - trunc_bf(p00), p01 - trunc_bf(p01));
                al[k2][1] = pack_bf16(p02 - trunc_bf(p02), p03 - trunc_bf(p03));
                al[k2][2] = pack_bf16(p10 - trunc_bf(p10), p11 - trunc_bf(p11));
                al[k2][3] = pack_bf16(p12 - trunc_bf(p12), p13 - trunc_bf(p13));
            }

            // ---- O += P V  (3-term: Ph*Vh + Pl*Vh + Ph*Vl), n = hd cols
            uint32_t vb = sb + 25600 + (lr + ((sel >> 1) << 3)) * (VSTR * 2)
                        + (((sel & 1) << 3)) * 2;
#pragma unroll
            for (int k2 = 0; k2 < 4; k2++) {
#pragma unroll
                for (int w = 0; w < 4; w++) {
                    uint32_t v4[4];
                    ldm_x4(v4, vb + (w * 16) * (VSTR * 2) + k2 * 32);
                    mma16816(oacc[2 * w],     ah[k2], v4);
                    mma16816(oacc[2 * w + 1], ah[k2], v4 + 2);
                    mma16816(oacc[2 * w],     al[k2], v4);
                    mma16816(oacc[2 * w + 1], al[k2], v4 + 2);
                    ldm_x4(v4, vb + 9216 + (w * 16) * (VSTR * 2) + k2 * 32);
                    mma16816(oacc[2 * w],     ah[k2], v4);
                    mma16816(oacc[2 * w + 1], ah[k2], v4 + 2);
                }
            }
        }
        __syncthreads();
    }

    // ---- epilogue
    float inv0 = 1.f / lrow0, inv1 = 1.f / lrow1;
    int b = bh >> 4, h = bh & 15;
    int r0 = q0 + wm * 16 + (lane >> 2);
#pragma unroll
    for (int nt = 0; nt < 8; nt++) {
        int col = h * HDIM + nt * 8 + (lane & 3) * 2;
        *(float2*)(O + (size_t)(b * TT + r0) * DD + col) =
            make_float2(oacc[nt][0] * inv0, oacc[nt][1] * inv0);
        *(float2*)(O + (size_t)(b * TT + r0 + 8) * DD + col) =
            make_float2(oacc[nt][2] * inv1, oacc[nt][3] * inv1);
    }
}

// ---------------- launch -----------------------------------------------------
extern "C" void kernel_launch(void* const* d_in, const int* in_sizes, int n_in,
                              void* d_out, int out_size)
{
    const float* x     = (const float*)d_in[0];
    const float* qkv_w = (const float*)d_in[1];
    const float* qkv_b = (const float*)d_in[2];
    const float* out_w = (const float*)d_in[3];
    const float* out_b = (const float*)d_in[4];
    float* out = (float*)d_out;

    float *qkv, *att;
    __nv_bfloat16 *a3, *bq3, *bo3, *q3, *k3, *vth, *vtl;
    cudaGetSymbolAddress((void**)&qkv, g_qkv);
    cudaGetSymbolAddress((void**)&att, g_att);
    cudaGetSymbolAddress((void**)&a3,  g_a3);
    cudaGetSymbolAddress((void**)&bq3, g_bq3);
    cudaGetSymbolAddress((void**)&bo3, g_bo3);
    cudaGetSymbolAddress((void**)&q3,  g_q3);
    cudaGetSymbolAddress((void**)&k3,  g_k3);
    cudaGetSymbolAddress((void**)&vth, g_vth);
    cudaGetSymbolAddress((void**)&vtl, g_vtl);

    cudaFuncSetAttribute(attn_mma, cudaFuncAttributeMaxDynamicSharedMemorySize,
                         ATT_SMEM);
    cudaFuncSetAttribute(gemm_mma, cudaFuncAttributeMaxDynamicSharedMemorySize,
                         GEMM_SMEM_MMA);

    // 0) bf16 hi/lo splits of x and W_qkv^T
    split_a<<<(M_ROWS * DD) / 256, 256>>>(x, a3, M_ROWS * DD);
    {
        dim3 g(N_QKV / 32, DD / 32);
        split_bt<<<g, 256>>>(qkv_w, bq3, N_QKV);
    }
    // 1) QKV projection via mma.sync
    {
        dim3 grid(N_QKV / 128, M_ROWS / 128);
        gemm_mma<<<grid, 256, GEMM_SMEM_MMA>>>(a3, bq3, qkv_b, qkv, N_QKV);
    }
    // 2) RoPE + split Q/K ; V transpose + split
    rope_split2<<<(BB * TT * NH * 32) / 256, 256>>>(qkv, q3, k3);
    {
        dim3 g(TT / 32, HDIM / 32, BH);
        vsplit_t<<<g, 256>>>(qkv, vth, vtl);
    }
    // 3) mma.sync flash attention
    {
        dim3 grid(TT / 128, BH);
        attn_mma<<<grid, 256, ATT_SMEM>>>(q3, k3, vth, vtl, att);
    }
    // 4) Output projection via mma.sync
    split_a<<<(M_ROWS * DD) / 256, 256>>>(att, a3, M_ROWS * DD);
    {
        dim3 g(DD / 32, DD / 32);
        split_bt<<<g, 256>>>(out_w, bo3, DD);
    }
    {
        dim3 grid(DD / 128, M_ROWS / 128);
        gemm_mma<<<grid, 256, GEMM_SMEM_MMA>>>(a3, bo3, out_b, out, DD);
    }
}

// round 13
// speedup vs baseline: 1.5135x; 1.5135x over previous
#include <cuda_runtime.h>
#include <cuda_bf16.h>
#include <stdint.h>
#include <math.h>

// Problem constants
#define BB 2
#define TT 2048
#define DD 1024
#define NH 16
#define HDIM 64
#define M_ROWS (BB*TT)          // 4096
#define N_QKV (3*DD)            // 3072
#define K3 (3*DD)               // split-K' = 3*1024
#define BH (BB*NH)              // 32

// ---------------- scratch (static device globals: allocation-free) ----------
__device__ float g_qkv[M_ROWS * N_QKV];                    // 4096 x 3072 fp32
__device__ __nv_bfloat16 g_a3 [M_ROWS * K3];               // [M, 3K] split A (reused)
__device__ __nv_bfloat16 g_bq3[N_QKV * K3];                // [N, 3K] split W_qkv^T
__device__ __nv_bfloat16 g_bo3[DD * K3];                   // [N, 3K] split W_out^T
__device__ __nv_bfloat16 g_q3 [BH * TT * 192];             // [bh][t][192] split Q (scaled)
__device__ __nv_bfloat16 g_k3 [BH * TT * 192];             // [bh][t][192] split K
__device__ __nv_bfloat16 g_vth[BH * HDIM * TT];            // [bh][d][t] V hi (transposed)
__device__ __nv_bfloat16 g_vtl[BH * HDIM * TT];            // [bh][d][t] V lo

// ======================= PTX helpers =========================================
__device__ __forceinline__ uint32_t smem_u32(const void* p) {
    uint32_t a;
    asm("{ .reg .u64 t; cvta.to.shared.u64 t, %1; cvt.u32.u64 %0, t; }"
        : "=r"(a) : "l"(p));
    return a;
}
#define CP_ASYNC16(dst, src) \
    asm volatile("cp.async.cg.shared.global [%0], [%1], 16;" \
                 :: "r"(dst), "l"(src) : "memory")
#define CP_COMMIT() asm volatile("cp.async.commit_group;" ::: "memory")
#define CP_WAIT1()  asm volatile("cp.async.wait_group 1;" ::: "memory")
#define CP_WAIT0()  asm volatile("cp.async.wait_group 0;" ::: "memory")

__device__ __forceinline__ void ldm_x4(uint32_t* r, uint32_t a) {
    asm volatile("ldmatrix.sync.aligned.m8n8.x4.shared.b16 {%0,%1,%2,%3}, [%4];"
                 : "=r"(r[0]), "=r"(r[1]), "=r"(r[2]), "=r"(r[3]) : "r"(a));
}
__device__ __forceinline__ void mma16816(float* c, const uint32_t* a,
                                         const uint32_t* b) {
    asm volatile(
        "mma.sync.aligned.m16n8k16.row.col.f32.bf16.bf16.f32 "
        "{%0,%1,%2,%3}, {%4,%5,%6,%7}, {%8,%9}, {%0,%1,%2,%3};"
        : "+f"(c[0]), "+f"(c[1]), "+f"(c[2]), "+f"(c[3])
        : "r"(a[0]), "r"(a[1]), "r"(a[2]), "r"(a[3]), "r"(b[0]), "r"(b[1]));
}
// pack {lo=trunc_bf16(a), hi=trunc_bf16(b)} in one PRMT
__device__ __forceinline__ uint32_t prmt_hi16(float a, float b) {
    uint32_t r;
    asm("prmt.b32 %0, %1, %2, 0x7632;"
        : "=r"(r) : "r"(__float_as_uint(a)), "r"(__float_as_uint(b)));
    return r;
}
__device__ __forceinline__ uint32_t pack_bf16(float lo, float hi) {
    uint32_t r;
    asm("cvt.rn.bf16x2.f32 %0, %1, %2;" : "=r"(r) : "f"(hi), "f"(lo));
    return r;
}
__device__ __forceinline__ float trunc_bf(float a) {
    return __uint_as_float(__float_as_uint(a) & 0xFFFF0000u);
}
// fast 2^t for t <= 0 on FMA/ALU pipes (no MUFU). |rel err| ~2e-6.
__device__ __forceinline__ float exp2p(float t) {
    t = fmaxf(t, -30.f);
    float fm = t + 12582912.f;                       // round-to-nearest int
    int n = __float_as_int(fm) - 0x4B400000;
    float f = t - (fm - 12582912.f);                 // [-0.5, 0.5]
    float p = 0.0013333558f;
    p = fmaf(p, f, 0.0096181291f);
    p = fmaf(p, f, 0.0555041087f);
    p = fmaf(p, f, 0.2402265069f);
    p = fmaf(p, f, 0.6931471806f);
    p = fmaf(p, f, 1.0f);
    return p * __int_as_float((n + 127) << 23);
}

// ======================= split / transpose kernels ===========================
__global__ __launch_bounds__(256) void split_a(
    const float* __restrict__ A, __nv_bfloat16* __restrict__ A3, int total)
{
    int idx = blockIdx.x * blockDim.x + threadIdx.x;
    if (idx >= total) return;
    int m = idx / DD, k = idx - m * DD;
    float a = A[idx];
    __nv_bfloat16 hi = __float2bfloat16(a);
    __nv_bfloat16 lo = __float2bfloat16(a - __bfloat162float(hi));
    size_t rb = (size_t)m * K3;
    A3[rb + k] = hi;
    A3[rb + DD + k] = hi;
    A3[rb + 2 * DD + k] = lo;
}

__global__ __launch_bounds__(256) void split_bt(
    const float* __restrict__ W, __nv_bfloat16* __restrict__ Bt3, int N)
{
    __shared__ float tile[32][33];
    int n0 = blockIdx.x * 32;
    int k0 = blockIdx.y * 32;
    int tx = threadIdx.x & 31;
    int ty = threadIdx.x >> 5;
    for (int r = ty; r < 32; r += 8)
        tile[r][tx] = W[(size_t)(k0 + r) * N + n0 + tx];
    __syncthreads();
    for (int r = ty; r < 32; r += 8) {
        int n = n0 + r;
        int k = k0 + tx;
        float w = tile[tx][r];
        __nv_bfloat16 hi = __float2bfloat16(w);
        __nv_bfloat16 lo = __float2bfloat16(w - __bfloat162float(hi));
        size_t rb = (size_t)n * K3;
        Bt3[rb + k] = hi;
        Bt3[rb + DD + k] = lo;
        Bt3[rb + 2 * DD + k] = hi;
    }
}

// ======================= mma.sync GEMM (2-stage, proven R10) =================
#define SM_STRIDE 40

__global__ __launch_bounds__(256, 2) void gemm_mma(
    const __nv_bfloat16* __restrict__ A, const __nv_bfloat16* __restrict__ Bt,
    const float* __restrict__ bias, float* __restrict__ C, int N)
{
    __shared__ __nv_bfloat16 sh[2][2][128][SM_STRIDE];

    const int tid = threadIdx.x;
    const int lane = tid & 31;
    const int wid = tid >> 5;
    const int wm = wid >> 2;
    const int wn = wid & 3;
    const int bm = blockIdx.y;
    const int bn = blockIdx.x;
    const int KCH = K3 / 32;

    const uint32_t shA0 = smem_u32(&sh[0][0][0][0]);
    const uint32_t stageBytes = 2 * 128 * SM_STRIDE * 2;
    const uint32_t abBytes = 128 * SM_STRIDE * 2;

    const int prow = tid >> 2;
    const int pseg = (tid & 3) * 8;
    const size_t arow0 = (size_t)(bm * 128 + prow) * K3 + pseg;
    const size_t brow0 = (size_t)(bn * 128 + prow) * K3 + pseg;
    const size_t arow1 = (size_t)(bm * 128 + prow + 64) * K3 + pseg;
    const size_t brow1 = (size_t)(bn * 128 + prow + 64) * K3 + pseg;
    const uint32_t dA0 = (prow * SM_STRIDE + pseg) * 2;
    const uint32_t dA1 = ((prow + 64) * SM_STRIDE + pseg) * 2;

    float c[4][4][4];
#pragma unroll
    for (int i = 0; i < 4; i++)
#pragma unroll
        for (int j = 0; j < 4; j++)
#pragma unroll
            for (int r = 0; r < 4; r++) c[i][j][r] = 0.f;

    const int lr = lane & 7;
    const int sel = lane >> 3;
    const uint32_t aRow = wm * 64 + lr + ((sel & 1) << 3);
    const uint32_t aCol = (sel >> 1) << 3;
    const uint32_t aOff = (aRow * SM_STRIDE + aCol) * 2;
    const uint32_t bRow = wn * 32 + lr + ((sel >> 1) << 3);
    const uint32_t bCol = (sel & 1) << 3;
    const uint32_t bOff = (bRow * SM_STRIDE + bCol) * 2;

    {
        CP_ASYNC16(shA0 + dA0, A + arow0);
        CP_ASYNC16(shA0 + abBytes + dA0, Bt + brow0);
        CP_ASYNC16(shA0 + dA1, A + arow1);
        CP_ASYNC16(shA0 + abBytes + dA1, Bt + brow1);
        CP_COMMIT();
    }

    for (int kc = 0; kc < KCH; kc++) {
        if (kc + 1 < KCH) {
            uint32_t sb = shA0 + ((kc + 1) & 1) * stageBytes;
            size_t ko = (size_t)(kc + 1) * 32;
            CP_ASYNC16(sb + dA0, A + arow0 + ko);
            CP_ASYNC16(sb + abBytes + dA0, Bt + brow0 + ko);
            CP_ASYNC16(sb + dA1, A + arow1 + ko);
            CP_ASYNC16(sb + abBytes + dA1, Bt + brow1 + ko);
            CP_COMMIT();
            CP_WAIT1();
        } else {
            CP_WAIT0();
        }
        __syncthreads();

        uint32_t sb = shA0 + (kc & 1) * stageBytes;
#pragma unroll
        for (int ks = 0; ks < 2; ks++) {
            uint32_t af[4][4], bf[4][2];
#pragma unroll
            for (int mi = 0; mi < 4; mi++)
                ldm_x4(af[mi], sb + aOff + (mi * 16 * SM_STRIDE + ks * 16) * 2);
#pragma unroll
            for (int p = 0; p < 2; p++) {
                uint32_t r4[4];
                ldm_x4(r4, sb + abBytes + bOff +
                           (p * 16 * SM_STRIDE + ks * 16) * 2);
                bf[p * 2][0] = r4[0]; bf[p * 2][1] = r4[1];
                bf[p * 2 + 1][0] = r4[2]; bf[p * 2 + 1][1] = r4[3];
            }
#pragma unroll
            for (int mi = 0; mi < 4; mi++)
#pragma unroll
                for (int nj = 0; nj < 4; nj++)
                    mma16816(c[mi][nj], af[mi], bf[nj]);
        }
        __syncthreads();
    }

    const int cn0 = bn * 128 + wn * 32 + (lane & 3) * 2;
    const int cm0 = bm * 128 + wm * 64 + (lane >> 2);
#pragma unroll
    for (int nj = 0; nj < 4; nj++) {
        int col = cn0 + nj * 8;
        float bv0 = bias[col], bv1 = bias[col + 1];
#pragma unroll
        for (int mi = 0; mi < 4; mi++) {
            int row = cm0 + mi * 16;
            float2 v0 = make_float2(c[mi][nj][0] + bv0, c[mi][nj][1] + bv1);
            float2 v1 = make_float2(c[mi][nj][2] + bv0, c[mi][nj][3] + bv1);
            *(float2*)(C + (size_t)row * N + col) = v0;
            *(float2*)(C + (size_t)(row + 8) * N + col) = v1;
        }
    }
}

// ---------------- RoPE -> split Q3/K3 ([bh][t][192] bf16) -------------------
// Q3 windows: [hi | hi | lo] (scaled by 0.125*log2(e));  K3: [hi | lo | hi].
__global__ __launch_bounds__(256) void rope_split2(
    const float* __restrict__ qkv,
    __nv_bfloat16* __restrict__ Q3, __nv_bfloat16* __restrict__ K3g)
{
    int idx = blockIdx.x * blockDim.x + threadIdx.x;
    int i = idx & 31;
    int h = (idx >> 5) & (NH - 1);
    int t = (idx >> 9) & (TT - 1);
    int b = idx >> 20;

    const float* base = qkv + (size_t)(b * TT + t) * N_QKV;
    const float* qs = base + h * HDIM;
    const float* ks = base + DD + h * HDIM;

    float tf = (float)t;
    float sn, cs;
    if (i < 16) {
        float f1 = tf * powf(10000.f, -(float)(4 * i) / 64.f);
        float f2 = tf * powf(10000.f, -(float)(4 * i + 2) / 64.f);
        sn = sinf(f1);
        cs = sinf(f2);
    } else {
        float f1 = tf * powf(10000.f, -(float)(4 * i - 64) / 64.f);
        float f2 = tf * powf(10000.f, -(float)(4 * i - 62) / 64.f);
        sn = cosf(f1);
        cs = cosf(f2);
    }

    const float QSC = 0.125f * 1.44269504f;   // scale * log2(e), folded into Q
    size_t ob = ((size_t)(b * NH + h) * TT + t) * 192;

    float q1 = qs[2 * i], q2 = qs[2 * i + 1];
    float qa = (q1 * cs - q2 * sn) * QSC;     // dim i
    float qb = (q1 * sn + q2 * cs) * QSC;     // dim 32+i
    __nv_bfloat16 qah = __float2bfloat16(qa);
    __nv_bfloat16 qbh = __float2bfloat16(qb);
    Q3[ob + i]       = qah;  Q3[ob + 64 + i]  = qah;
    Q3[ob + 128 + i] = __float2bfloat16(qa - __bfloat162float(qah));
    Q3[ob + 32 + i]  = qbh;  Q3[ob + 96 + i]  = qbh;
    Q3[ob + 160 + i] = __float2bfloat16(qb - __bfloat162float(qbh));

    float k1 = ks[2 * i], k2 = ks[2 * i + 1];
    float ka = k1 * cs - k2 * sn;
    float kb = k1 * sn + k2 * cs;
    __nv_bfloat16 kah = __float2bfloat16(ka);
    __nv_bfloat16 kbh = __float2bfloat16(kb);
    K3g[ob + i]       = kah;
    K3g[ob + 64 + i]  = __float2bfloat16(ka - __bfloat162float(kah));
    K3g[ob + 128 + i] = kah;
    K3g[ob + 32 + i]  = kbh;
    K3g[ob + 96 + i]  = __float2bfloat16(kb - __bfloat162float(kbh));
    K3g[ob + 160 + i] = kbh;
}

// ---------------- V transpose + hi/lo split: [bh][d][t] ---------------------
__global__ __launch_bounds__(256) void vsplit_t(
    const float* __restrict__ qkv,
    __nv_bfloat16* __restrict__ Vh, __nv_bfloat16* __restrict__ Vl)
{
    __shared__ float tile[32][33];
    int t0 = blockIdx.x * 32;
    int d0 = blockIdx.y * 32;
    int bh = blockIdx.z;
    int b = bh >> 4, h = bh & 15;
    int tx = threadIdx.x & 31;
    int ty = threadIdx.x >> 5;
    const float* src = qkv + ((size_t)(b * TT) + t0) * N_QKV + 2 * DD + h * HDIM + d0;
    for (int r = ty; r < 32; r += 8)
        tile[r][tx] = src[(size_t)r * N_QKV + tx];
    __syncthreads();
    for (int r = ty; r < 32; r += 8) {
        float v = tile[tx][r];                   // t = t0+tx, d = d0+r
        __nv_bfloat16 hi = __float2bfloat16(v);
        size_t o = ((size_t)bh * HDIM + d0 + r) * TT + t0 + tx;
        Vh[o] = hi;
        Vl[o] = __float2bfloat16(v - __bfloat162float(hi));
    }
}

// ======================= mma.sync flash attention ============================
// Block = 128 q rows of one (b,h); 8 warps, m16 each; KV tiles of 64.
// Epilogue writes the hi/lo 3-window split A3 for the out-projection directly.
#define QSTR 200                 // padded bf16 stride (conflict-free ldmatrix)
#define KSTR 200
#define VSTR 72
#define ATT_STG 44032            // K 25600 + Vh 9216 + Vl 9216
#define ATT_SMEM (2 * ATT_STG)   // 88064

__global__ __launch_bounds__(256, 1) void attn_mma(
    const __nv_bfloat16* __restrict__ Q3, const __nv_bfloat16* __restrict__ K3g,
    const __nv_bfloat16* __restrict__ Vh, const __nv_bfloat16* __restrict__ Vl,
    __nv_bfloat16* __restrict__ A3)
{
    extern __shared__ char smem[];
    const uint32_t su = smem_u32(smem);
    const int tid = threadIdx.x;
    const int lane = tid & 31;
    const int wm = tid >> 5;        // warp = 16 q rows
    const int qt = (int)gridDim.x - 1 - (int)blockIdx.x;   // LPT: big tiles first
    const int bh = blockIdx.y;
    const int q0 = qt * 128;
    const int jmax = 2 * qt + 2;

    const __nv_bfloat16* Qg  = Q3  + (size_t)bh * TT * 192;
    const __nv_bfloat16* Kg  = K3g + (size_t)bh * TT * 192;
    const __nv_bfloat16* Vhg = Vh  + (size_t)bh * HDIM * TT;
    const __nv_bfloat16* Vlg = Vl  + (size_t)bh * HDIM * TT;

    // ---- stage Q tile (128 x 192) and extract A-fragments, then free smem
#pragma unroll
    for (int c = 0; c < 12; c++) {
        int g = tid + 256 * c;
        int row = g / 24, seg = g % 24;
        CP_ASYNC16(su + row * (QSTR * 2) + seg * 16,
                   Qg + (size_t)(q0 + row) * 192 + seg * 8);
    }
    CP_COMMIT(); CP_WAIT0();
    __syncthreads();

    const int lr = lane & 7;
    const int sel = lane >> 3;
    uint32_t qf[12][4];
    {
        uint32_t ab = su + (wm * 16 + lr + ((sel & 1) << 3)) * (QSTR * 2)
                    + (((sel >> 1) << 3)) * 2;
#pragma unroll
        for (int kk = 0; kk < 12; kk++)
            ldm_x4(qf[kk], ab + kk * 32);
    }
    __syncthreads();

    float oacc[8][4];
#pragma unroll
    for (int i = 0; i < 8; i++)
#pragma unroll
        for (int j = 0; j < 4; j++) oacc[i][j] = 0.f;
    float mrow0 = -1e30f, mrow1 = -1e30f, lrow0 = 0.f, lrow1 = 0.f;

    auto issue = [&](int jt2) {
        int j0p = jt2 * 64;
        uint32_t sb = su + (jt2 & 1) * ATT_STG;
#pragma unroll
        for (int c = 0; c < 6; c++) {
            int g = tid + 256 * c;
            int row = g / 24, seg = g % 24;
            CP_ASYNC16(sb + row * (KSTR * 2) + seg * 16,
                       Kg + (size_t)(j0p + row) * 192 + seg * 8);
        }
#pragma unroll
        for (int c = 0; c < 2; c++) {
            int g = tid + 256 * c;
            int row = g >> 3, seg = g & 7;
            CP_ASYNC16(sb + 25600 + row * (VSTR * 2) + seg * 16,
                       Vhg + (size_t)row * TT + j0p + seg * 8);
            CP_ASYNC16(sb + 34816 + row * (VSTR * 2) + seg * 16,
                       Vlg + (size_t)row * TT + j0p + seg * 8);
        }
    };

    issue(0); CP_COMMIT();

    for (int jt = 0; jt < jmax; jt++) {
        if (jt + 1 < jmax) { issue(jt + 1); CP_COMMIT(); CP_WAIT1(); }
        else CP_WAIT0();
        __syncthreads();

        const int j0 = jt * 64;
        if (j0 <= q0 + wm * 16 + 15) {          // warp has unmasked work
            uint32_t sb = su + (jt & 1) * ATT_STG;

            // ---- S = Q K^T (n = kv cols 0..63)
            float sacc[8][4];
#pragma unroll
            for (int i = 0; i < 8; i++)
#pragma unroll
                for (int j = 0; j < 4; j++) sacc[i][j] = 0.f;

            uint32_t kb = sb + (lr + ((sel >> 1) << 3)) * (KSTR * 2)
                        + (((sel & 1) << 3)) * 2;
#pragma unroll
            for (int kk = 0; kk < 12; kk++) {
#pragma unroll
                for (int w = 0; w < 4; w++) {
                    uint32_t r4[4];
                    ldm_x4(r4, kb + (w * 16) * (KSTR * 2) + kk * 32);
                    mma16816(sacc[2 * w],     qf[kk], r4);
                    mma16816(sacc[2 * w + 1], qf[kk], r4 + 2);
                }
            }

            // ---- causal mask (diagonal region only)
            int r0 = q0 + wm * 16 + (lane >> 2);
            if (j0 + 63 > q0 + wm * 16) {
#pragma unroll
                for (int nt = 0; nt < 8; nt++) {
                    int cb = j0 + nt * 8 + (lane & 3) * 2;
                    if (cb     > r0)     sacc[nt][0] = -1e30f;
                    if (cb + 1 > r0)     sacc[nt][1] = -1e30f;
                    if (cb     > r0 + 8) sacc[nt][2] = -1e30f;
                    if (cb + 1 > r0 + 8) sacc[nt][3] = -1e30f;
                }
            }

            // ---- online softmax (base-2, poly exp on FMA pipe)
            float mx0 = -1e30f, mx1 = -1e30f;
#pragma unroll
            for (int nt = 0; nt < 8; nt++) {
                mx0 = fmaxf(mx0, fmaxf(sacc[nt][0], sacc[nt][1]));
                mx1 = fmaxf(mx1, fmaxf(sacc[nt][2], sacc[nt][3]));
            }
            mx0 = fmaxf(mx0, __shfl_xor_sync(0xffffffffu, mx0, 1));
            mx0 = fmaxf(mx0, __shfl_xor_sync(0xffffffffu, mx0, 2));
            mx1 = fmaxf(mx1, __shfl_xor_sync(0xffffffffu, mx1, 1));
            mx1 = fmaxf(mx1, __shfl_xor_sync(0xffffffffu, mx1, 2));
            float mn0 = fmaxf(mrow0, mx0), mn1 = fmaxf(mrow1, mx1);
            float a0 = exp2p(mrow0 - mn0), a1 = exp2p(mrow1 - mn1);
            mrow0 = mn0; mrow1 = mn1;
            lrow0 *= a0; lrow1 *= a1;
#pragma unroll
            for (int nt = 0; nt < 8; nt++) {
                oacc[nt][0] *= a0; oacc[nt][1] *= a0;
                oacc[nt][2] *= a1; oacc[nt][3] *= a1;
            }
            float rs0 = 0.f, rs1 = 0.f;
#pragma unroll
            for (int nt = 0; nt < 8; nt++) {
                sacc[nt][0] = exp2p(sacc[nt][0] - mn0);
                sacc[nt][1] = exp2p(sacc[nt][1] - mn0);
                sacc[nt][2] = exp2p(sacc[nt][2] - mn1);
                sacc[nt][3] = exp2p(sacc[nt][3] - mn1);
                rs0 += sacc[nt][0] + sacc[nt][1];
                rs1 += sacc[nt][2] + sacc[nt][3];
            }
            rs0 += __shfl_xor_sync(0xffffffffu, rs0, 1);
            rs0 += __shfl_xor_sync(0xffffffffu, rs0, 2);
            rs1 += __shfl_xor_sync(0xffffffffu, rs1, 1);
            rs1 += __shfl_xor_sync(0xffffffffu, rs1, 2);
            lrow0 += rs0; lrow1 += rs1;

            // ---- pack P hi (truncate) / lo into A-fragments
            uint32_t ah[4][4], al[4][4];
#pragma unroll
            for (int k2 = 0; k2 < 4; k2++) {
                float p00 = sacc[2 * k2][0],     p01 = sacc[2 * k2][1];
                float p02 = sacc[2 * k2][2],     p03 = sacc[2 * k2][3];
                float p10 = sacc[2 * k2 + 1][0], p11 = sacc[2 * k2 + 1][1];
                float p12 = sacc[2 * k2 + 1][2], p13 = sacc[2 * k2 + 1][3];
                ah[k2][0] = prmt_hi16(p00, p01);
                ah[k2][1] = prmt_hi16(p02, p03);
                ah[k2][2] = prmt_hi16(p10, p11);
                ah[k2][3] = prmt_hi16(p12, p13);
                al[k2][0] = pack_bf16(p00 - trunc_bf(p00), p01 - trunc_bf(p01));
                al[k2][1] = pack_bf16(p02 - trunc_bf(p02), p03 - trunc_bf(p03));
                al[k2][2] = pack_bf16(p10 - trunc_bf(p10), p11 - trunc_bf(p11));
                al[k2][3] = pack_bf16(p12 - trunc_bf(p12), p13 - trunc_bf(p13));
            }

            // ---- O += P V  (3-term: Ph*Vh + Pl*Vh + Ph*Vl), n = hd cols
            uint32_t vb = sb + 25600 + (lr + ((sel >> 1) << 3)) * (VSTR * 2)
                        + (((sel & 1) << 3)) * 2;
#pragma unroll
            for (int k2 = 0; k2 < 4; k2++) {
#pragma unroll
                for (int w = 0; w < 4; w++) {
                    uint32_t v4[4];
                    ldm_x4(v4, vb + (w * 16) * (VSTR * 2) + k2 * 32);
                    mma16816(oacc[2 * w],     ah[k2], v4);
                    mma16816(oacc[2 * w + 1], ah[k2], v4 + 2);
                    mma16816(oacc[2 * w],     al[k2], v4);
                    mma16816(oacc[2 * w + 1], al[k2], v4 + 2);
                    ldm_x4(v4, vb + 9216 + (w * 16) * (VSTR * 2) + k2 * 32);
                    mma16816(oacc[2 * w],     ah[k2], v4);
                    mma16816(oacc[2 * w + 1], ah[k2], v4 + 2);
                }
            }
        }
        __syncthreads();
    }

    // ---- epilogue: write hi/lo split A3 for out-projection directly
    float inv0 = 1.f / lrow0, inv1 = 1.f / lrow1;
    int b = bh >> 4, h = bh & 15;
    int r0 = q0 + wm * 16 + (lane >> 2);
#pragma unroll
    for (int nt = 0; nt < 8; nt++) {
        int col = h * HDIM + nt * 8 + (lane & 3) * 2;
#pragma unroll
        for (int half = 0; half < 2; half++) {
            float v0 = oacc[nt][2 * half]     * (half ? inv1 : inv0);
            float v1 = oacc[nt][2 * half + 1] * (half ? inv1 : inv0);
            float h0 = __bfloat162float(__float2bfloat16(v0));
            float h1 = __bfloat162float(__float2bfloat16(v1));
            uint32_t whi = pack_bf16(v0, v1);
            uint32_t wlo = pack_bf16(v0 - h0, v1 - h1);
            size_t rb = (size_t)(b * TT + r0 + half * 8) * K3;
            *(uint32_t*)((char*)(A3 + rb + col) )           = whi;
            *(uint32_t*)((char*)(A3 + rb + DD + col) )      = whi;
            *(uint32_t*)((char*)(A3 + rb + 2 * DD + col) )  = wlo;
        }
    }
}

// ---------------- launch -----------------------------------------------------
extern "C" void kernel_launch(void* const* d_in, const int* in_sizes, int n_in,
                              void* d_out, int out_size)
{
    const float* x     = (const float*)d_in[0];
    const float* qkv_w = (const float*)d_in[1];
    const float* qkv_b = (const float*)d_in[2];
    const float* out_w = (const float*)d_in[3];
    const float* out_b = (const float*)d_in[4];
    float* out = (float*)d_out;

    float *qkv;
    __nv_bfloat16 *a3, *bq3, *bo3, *q3, *k3, *vth, *vtl;
    cudaGetSymbolAddress((void**)&qkv, g_qkv);
    cudaGetSymbolAddress((void**)&a3,  g_a3);
    cudaGetSymbolAddress((void**)&bq3, g_bq3);
    cudaGetSymbolAddress((void**)&bo3, g_bo3);
    cudaGetSymbolAddress((void**)&q3,  g_q3);
    cudaGetSymbolAddress((void**)&k3,  g_k3);
    cudaGetSymbolAddress((void**)&vth, g_vth);
    cudaGetSymbolAddress((void**)&vtl, g_vtl);

    cudaFuncSetAttribute(attn_mma, cudaFuncAttributeMaxDynamicSharedMemorySize,
                         ATT_SMEM);

    // 0) bf16 hi/lo splits of x and W_qkv^T
    split_a<<<(M_ROWS * DD) / 256, 256>>>(x, a3, M_ROWS * DD);
    {
        dim3 g(N_QKV / 32, DD / 32);
        split_bt<<<g, 256>>>(qkv_w, bq3, N_QKV);
    }
    // 1) QKV projection via mma.sync
    {
        dim3 grid(N_QKV / 128, M_ROWS / 128);
        gemm_mma<<<grid, 256>>>(a3, bq3, qkv_b, qkv, N_QKV);
    }
    // 2) RoPE + split Q/K ; V transpose + split
    rope_split2<<<(BB * TT * NH * 32) / 256, 256>>>(qkv, q3, k3);
    {
        dim3 g(TT / 32, HDIM / 32, BH);
        vsplit_t<<<g, 256>>>(qkv, vth, vtl);
    }
    // 3) mma.sync flash attention (writes split A3 directly)
    {
        dim3 grid(TT / 128, BH);
        attn_mma<<<grid, 256, ATT_SMEM>>>(q3, k3, vth, vtl, a3);
    }
    // 4) Output projection via mma.sync
    {
        dim3 g(DD / 32, DD / 32);
        split_bt<<<g, 256>>>(out_w, bo3, DD);
    }
    {
        dim3 grid(DD / 128, M_ROWS / 128);
        gemm_mma<<<grid, 256>>>(a3, bo3, out_b, out, DD);
    }
}

// round 14
// speedup vs baseline: 1.5411x; 1.0182x over previous
#include <cuda_runtime.h>
#include <cuda_bf16.h>
#include <stdint.h>
#include <math.h>

// Problem constants
#define BB 2
#define TT 2048
#define DD 1024
#define NH 16
#define HDIM 64
#define M_ROWS (BB*TT)          // 4096
#define N_QKV (3*DD)            // 3072
#define K3 (3*DD)               // split-K' = 3*1024
#define BH (BB*NH)              // 32

// ---------------- scratch (static device globals: allocation-free) ----------
__device__ float g_qkv[M_ROWS * N_QKV];                    // 4096 x 3072 fp32
__device__ __nv_bfloat16 g_a3 [M_ROWS * K3];               // [M, 3K] split A (reused)
__device__ __nv_bfloat16 g_bq3[N_QKV * K3];                // [N, 3K] split W_qkv^T
__device__ __nv_bfloat16 g_bo3[DD * K3];                   // [N, 3K] split W_out^T
__device__ __nv_bfloat16 g_q3 [BH * TT * 192];             // [bh][t][192] split Q (scaled)
__device__ __nv_bfloat16 g_k3 [BH * TT * 192];             // [bh][t][192] split K
__device__ __nv_bfloat16 g_vth[BH * HDIM * TT];            // [bh][d][t] V hi (transposed)
__device__ __nv_bfloat16 g_vtl[BH * HDIM * TT];            // [bh][d][t] V lo

// ======================= PTX helpers =========================================
__device__ __forceinline__ uint32_t smem_u32(const void* p) {
    uint32_t a;
    asm("{ .reg .u64 t; cvta.to.shared.u64 t, %1; cvt.u32.u64 %0, t; }"
        : "=r"(a) : "l"(p));
    return a;
}
#define CP_ASYNC16(dst, src) \
    asm volatile("cp.async.cg.shared.global [%0], [%1], 16;" \
                 :: "r"(dst), "l"(src) : "memory")
#define CP_COMMIT() asm volatile("cp.async.commit_group;" ::: "memory")
#define CP_WAIT1()  asm volatile("cp.async.wait_group 1;" ::: "memory")
#define CP_WAIT0()  asm volatile("cp.async.wait_group 0;" ::: "memory")

__device__ __forceinline__ void ldm_x4(uint32_t* r, uint32_t a) {
    asm volatile("ldmatrix.sync.aligned.m8n8.x4.shared.b16 {%0,%1,%2,%3}, [%4];"
                 : "=r"(r[0]), "=r"(r[1]), "=r"(r[2]), "=r"(r[3]) : "r"(a));
}
__device__ __forceinline__ void mma16816(float* c, const uint32_t* a,
                                         const uint32_t* b) {
    asm volatile(
        "mma.sync.aligned.m16n8k16.row.col.f32.bf16.bf16.f32 "
        "{%0,%1,%2,%3}, {%4,%5,%6,%7}, {%8,%9}, {%0,%1,%2,%3};"
        : "+f"(c[0]), "+f"(c[1]), "+f"(c[2]), "+f"(c[3])
        : "r"(a[0]), "r"(a[1]), "r"(a[2]), "r"(a[3]), "r"(b[0]), "r"(b[1]));
}
// pack {lo=trunc_bf16(a), hi=trunc_bf16(b)} in one PRMT
__device__ __forceinline__ uint32_t prmt_hi16(float a, float b) {
    uint32_t r;
    asm("prmt.b32 %0, %1, %2, 0x7632;"
        : "=r"(r) : "r"(__float_as_uint(a)), "r"(__float_as_uint(b)));
    return r;
}
__device__ __forceinline__ uint32_t pack_bf16(float lo, float hi) {
    uint32_t r;
    asm("cvt.rn.bf16x2.f32 %0, %1, %2;" : "=r"(r) : "f"(hi), "f"(lo));
    return r;
}
__device__ __forceinline__ float trunc_bf(float a) {
    return __uint_as_float(__float_as_uint(a) & 0xFFFF0000u);
}
// fast 2^t for t <= 0 on FMA/ALU pipes (no MUFU). |rel err| ~2e-6.
__device__ __forceinline__ float exp2p(float t) {
    t = fmaxf(t, -30.f);
    float fm = t + 12582912.f;                       // round-to-nearest int
    int n = __float_as_int(fm) - 0x4B400000;
    float f = t - (fm - 12582912.f);                 // [-0.5, 0.5]
    float p = 0.0013333558f;
    p = fmaf(p, f, 0.0096181291f);
    p = fmaf(p, f, 0.0555041087f);
    p = fmaf(p, f, 0.2402265069f);
    p = fmaf(p, f, 0.6931471806f);
    p = fmaf(p, f, 1.0f);
    return p * __int_as_float((n + 127) << 23);
}

// ======================= split / transpose kernels ===========================
__global__ __launch_bounds__(256) void split_a(
    const float* __restrict__ A, __nv_bfloat16* __restrict__ A3, int total)
{
    int idx = blockIdx.x * blockDim.x + threadIdx.x;
    if (idx >= total) return;
    int m = idx / DD, k = idx - m * DD;
    float a = A[idx];
    __nv_bfloat16 hi = __float2bfloat16(a);
    __nv_bfloat16 lo = __float2bfloat16(a - __bfloat162float(hi));
    size_t rb = (size_t)m * K3;
    A3[rb + k] = hi;
    A3[rb + DD + k] = hi;
    A3[rb + 2 * DD + k] = lo;
}

__global__ __launch_bounds__(256) void split_bt(
    const float* __restrict__ W, __nv_bfloat16* __restrict__ Bt3, int N)
{
    __shared__ float tile[32][33];
    int n0 = blockIdx.x * 32;
    int k0 = blockIdx.y * 32;
    int tx = threadIdx.x & 31;
    int ty = threadIdx.x >> 5;
    for (int r = ty; r < 32; r += 8)
        tile[r][tx] = W[(size_t)(k0 + r) * N + n0 + tx];
    __syncthreads();
    for (int r = ty; r < 32; r += 8) {
        int n = n0 + r;
        int k = k0 + tx;
        float w = tile[tx][r];
        __nv_bfloat16 hi = __float2bfloat16(w);
        __nv_bfloat16 lo = __float2bfloat16(w - __bfloat162float(hi));
        size_t rb = (size_t)n * K3;
        Bt3[rb + k] = hi;
        Bt3[rb + DD + k] = lo;
        Bt3[rb + 2 * DD + k] = hi;
    }
}

// ======================= mma.sync GEMM (3-stage, 1 barrier/chunk) ============
#define SM_STRIDE 40
#define G_STAGE (2 * 128 * SM_STRIDE * 2)       // A+B per stage = 20480 B
#define G_AB (128 * SM_STRIDE * 2)              // 10240 B
#define GEMM_SMEM_MMA (3 * G_STAGE)             // 61440 B

__global__ __launch_bounds__(256, 2) void gemm_mma(
    const __nv_bfloat16* __restrict__ A, const __nv_bfloat16* __restrict__ Bt,
    const float* __restrict__ bias, float* __restrict__ C, int N)
{
    extern __shared__ char smem[];

    const int tid = threadIdx.x;
    const int lane = tid & 31;
    const int wid = tid >> 5;
    const int wm = wid >> 2;
    const int wn = wid & 3;
    const int bm = blockIdx.y;
    const int bn = blockIdx.x;
    const int KCH = K3 / 32;                    // 96

    const uint32_t shA0 = smem_u32(smem);

    const int prow = tid >> 2;
    const int pseg = (tid & 3) * 8;
    const size_t arow0 = (size_t)(bm * 128 + prow) * K3 + pseg;
    const size_t brow0 = (size_t)(bn * 128 + prow) * K3 + pseg;
    const size_t arow1 = (size_t)(bm * 128 + prow + 64) * K3 + pseg;
    const size_t brow1 = (size_t)(bn * 128 + prow + 64) * K3 + pseg;
    const uint32_t dA0 = (prow * SM_STRIDE + pseg) * 2;
    const uint32_t dA1 = ((prow + 64) * SM_STRIDE + pseg) * 2;

    float c[4][4][4];
#pragma unroll
    for (int i = 0; i < 4; i++)
#pragma unroll
        for (int j = 0; j < 4; j++)
#pragma unroll
            for (int r = 0; r < 4; r++) c[i][j][r] = 0.f;

    const int lr = lane & 7;
    const int sel = lane >> 3;
    const uint32_t aRow = wm * 64 + lr + ((sel & 1) << 3);
    const uint32_t aCol = (sel >> 1) << 3;
    const uint32_t aOff = (aRow * SM_STRIDE + aCol) * 2;
    const uint32_t bRow = wn * 32 + lr + ((sel >> 1) << 3);
    const uint32_t bCol = (sel & 1) << 3;
    const uint32_t bOff = (bRow * SM_STRIDE + bCol) * 2;

    auto issue = [&](int chunk) {
        uint32_t sb = shA0 + (uint32_t)(chunk % 3) * G_STAGE;
        size_t ko = (size_t)chunk * 32;
        CP_ASYNC16(sb + dA0, A + arow0 + ko);
        CP_ASYNC16(sb + G_AB + dA0, Bt + brow0 + ko);
        CP_ASYNC16(sb + dA1, A + arow1 + ko);
        CP_ASYNC16(sb + G_AB + dA1, Bt + brow1 + ko);
    };

    issue(0); CP_COMMIT();
    issue(1); CP_COMMIT();

    for (int kc = 0; kc < KCH; kc++) {
        if (kc + 1 < KCH) CP_WAIT1(); else CP_WAIT0();
        __syncthreads();
        if (kc + 2 < KCH) { issue(kc + 2); CP_COMMIT(); }

        uint32_t sb = shA0 + (uint32_t)(kc % 3) * G_STAGE;
#pragma unroll
        for (int ks = 0; ks < 2; ks++) {
            uint32_t af[4][4], bf[4][2];
#pragma unroll
            for (int mi = 0; mi < 4; mi++)
                ldm_x4(af[mi], sb + aOff + (mi * 16 * SM_STRIDE + ks * 16) * 2);
#pragma unroll
            for (int p = 0; p < 2; p++) {
                uint32_t r4[4];
                ldm_x4(r4, sb + G_AB + bOff +
                           (p * 16 * SM_STRIDE + ks * 16) * 2);
                bf[p * 2][0] = r4[0]; bf[p * 2][1] = r4[1];
                bf[p * 2 + 1][0] = r4[2]; bf[p * 2 + 1][1] = r4[3];
            }
#pragma unroll
            for (int mi = 0; mi < 4; mi++)
#pragma unroll
                for (int nj = 0; nj < 4; nj++)
                    mma16816(c[mi][nj], af[mi], bf[nj]);
        }
    }

    const int cn0 = bn * 128 + wn * 32 + (lane & 3) * 2;
    const int cm0 = bm * 128 + wm * 64 + (lane >> 2);
#pragma unroll
    for (int nj = 0; nj < 4; nj++) {
        int col = cn0 + nj * 8;
        float bv0 = bias[col], bv1 = bias[col + 1];
#pragma unroll
        for (int mi = 0; mi < 4; mi++) {
            int row = cm0 + mi * 16;
            float2 v0 = make_float2(c[mi][nj][0] + bv0, c[mi][nj][1] + bv1);
            float2 v1 = make_float2(c[mi][nj][2] + bv0, c[mi][nj][3] + bv1);
            *(float2*)(C + (size_t)row * N + col) = v0;
            *(float2*)(C + (size_t)(row + 8) * N + col) = v1;
        }
    }
}

// ---------------- RoPE -> split Q3/K3 ([bh][t][192] bf16) -------------------
// Q3 windows: [hi | hi | lo] (scaled by 0.125*log2(e));  K3: [hi | lo | hi].
__global__ __launch_bounds__(256) void rope_split2(
    const float* __restrict__ qkv,
    __nv_bfloat16* __restrict__ Q3, __nv_bfloat16* __restrict__ K3g)
{
    int idx = blockIdx.x * blockDim.x + threadIdx.x;
    int i = idx & 31;
    int h = (idx >> 5) & (NH - 1);
    int t = (idx >> 9) & (TT - 1);
    int b = idx >> 20;

    const float* base = qkv + (size_t)(b * TT + t) * N_QKV;
    const float* qs = base + h * HDIM;
    const float* ks = base + DD + h * HDIM;

    float tf = (float)t;
    float sn, cs;
    if (i < 16) {
        float f1 = tf * powf(10000.f, -(float)(4 * i) / 64.f);
        float f2 = tf * powf(10000.f, -(float)(4 * i + 2) / 64.f);
        sn = sinf(f1);
        cs = sinf(f2);
    } else {
        float f1 = tf * powf(10000.f, -(float)(4 * i - 64) / 64.f);
        float f2 = tf * powf(10000.f, -(float)(4 * i - 62) / 64.f);
        sn = cosf(f1);
        cs = cosf(f2);
    }

    const float QSC = 0.125f * 1.44269504f;   // scale * log2(e), folded into Q
    size_t ob = ((size_t)(b * NH + h) * TT + t) * 192;

    float q1 = qs[2 * i], q2 = qs[2 * i + 1];
    float qa = (q1 * cs - q2 * sn) * QSC;     // dim i
    float qb = (q1 * sn + q2 * cs) * QSC;     // dim 32+i
    __nv_bfloat16 qah = __float2bfloat16(qa);
    __nv_bfloat16 qbh = __float2bfloat16(qb);
    Q3[ob + i]       = qah;  Q3[ob + 64 + i]  = qah;
    Q3[ob + 128 + i] = __float2bfloat16(qa - __bfloat162float(qah));
    Q3[ob + 32 + i]  = qbh;  Q3[ob + 96 + i]  = qbh;
    Q3[ob + 160 + i] = __float2bfloat16(qb - __bfloat162float(qbh));

    float k1 = ks[2 * i], k2 = ks[2 * i + 1];
    float ka = k1 * cs - k2 * sn;
    float kb = k1 * sn + k2 * cs;
    __nv_bfloat16 kah = __float2bfloat16(ka);
    __nv_bfloat16 kbh = __float2bfloat16(kb);
    K3g[ob + i]       = kah;
    K3g[ob + 64 + i]  = __float2bfloat16(ka - __bfloat162float(kah));
    K3g[ob + 128 + i] = kah;
    K3g[ob + 32 + i]  = kbh;
    K3g[ob + 96 + i]  = __float2bfloat16(kb - __bfloat162float(kbh));
    K3g[ob + 160 + i] = kbh;
}

// ---------------- V transpose + hi/lo split: [bh][d][t] ---------------------
__global__ __launch_bounds__(256) void vsplit_t(
    const float* __restrict__ qkv,
    __nv_bfloat16* __restrict__ Vh, __nv_bfloat16* __restrict__ Vl)
{
    __shared__ float tile[32][33];
    int t0 = blockIdx.x * 32;
    int d0 = blockIdx.y * 32;
    int bh = blockIdx.z;
    int b = bh >> 4, h = bh & 15;
    int tx = threadIdx.x & 31;
    int ty = threadIdx.x >> 5;
    const float* src = qkv + ((size_t)(b * TT) + t0) * N_QKV + 2 * DD + h * HDIM + d0;
    for (int r = ty; r < 32; r += 8)
        tile[r][tx] = src[(size_t)r * N_QKV + tx];
    __syncthreads();
    for (int r = ty; r < 32; r += 8) {
        float v = tile[tx][r];                   // t = t0+tx, d = d0+r
        __nv_bfloat16 hi = __float2bfloat16(v);
        size_t o = ((size_t)bh * HDIM + d0 + r) * TT + t0 + tx;
        Vh[o] = hi;
        Vl[o] = __float2bfloat16(v - __bfloat162float(hi));
    }
}

// ======================= mma.sync flash attention ============================
// Block = 128 q rows of one (b,h); 8 warps, m16 each; KV tiles of 64.
// Epilogue writes the hi/lo 3-window split A3 for the out-projection directly.
#define QSTR 200                 // padded bf16 stride (conflict-free ldmatrix)
#define KSTR 200
#define VSTR 72
#define ATT_STG 44032            // K 25600 + Vh 9216 + Vl 9216
#define ATT_SMEM (2 * ATT_STG)   // 88064

__global__ __launch_bounds__(256, 1) void attn_mma(
    const __nv_bfloat16* __restrict__ Q3, const __nv_bfloat16* __restrict__ K3g,
    const __nv_bfloat16* __restrict__ Vh, const __nv_bfloat16* __restrict__ Vl,
    __nv_bfloat16* __restrict__ A3)
{
    extern __shared__ char smem[];
    const uint32_t su = smem_u32(smem);
    const int tid = threadIdx.x;
    const int lane = tid & 31;
    const int wm = tid >> 5;        // warp = 16 q rows
    const int qt = (int)gridDim.x - 1 - (int)blockIdx.x;   // LPT: big tiles first
    const int bh = blockIdx.y;
    const int q0 = qt * 128;
    const int jmax = 2 * qt + 2;

    const __nv_bfloat16* Qg  = Q3  + (size_t)bh * TT * 192;
    const __nv_bfloat16* Kg  = K3g + (size_t)bh * TT * 192;
    const __nv_bfloat16* Vhg = Vh  + (size_t)bh * HDIM * TT;
    const __nv_bfloat16* Vlg = Vl  + (size_t)bh * HDIM * TT;

    // ---- stage Q tile (128 x 192) and extract A-fragments, then free smem
#pragma unroll
    for (int c = 0; c < 12; c++) {
        int g = tid + 256 * c;
        int row = g / 24, seg = g % 24;
        CP_ASYNC16(su + row * (QSTR * 2) + seg * 16,
                   Qg + (size_t)(q0 + row) * 192 + seg * 8);
    }
    CP_COMMIT(); CP_WAIT0();
    __syncthreads();

    const int lr = lane & 7;
    const int sel = lane >> 3;
    uint32_t qf[12][4];
    {
        uint32_t ab = su + (wm * 16 + lr + ((sel & 1) << 3)) * (QSTR * 2)
                    + (((sel >> 1) << 3)) * 2;
#pragma unroll
        for (int kk = 0; kk < 12; kk++)
            ldm_x4(qf[kk], ab + kk * 32);
    }
    __syncthreads();

    float oacc[8][4];
#pragma unroll
    for (int i = 0; i < 8; i++)
#pragma unroll
        for (int j = 0; j < 4; j++) oacc[i][j] = 0.f;
    float mrow0 = -1e30f, mrow1 = -1e30f, lrow0 = 0.f, lrow1 = 0.f;

    auto issue = [&](int jt2) {
        int j0p = jt2 * 64;
        uint32_t sb = su + (jt2 & 1) * ATT_STG;
#pragma unroll
        for (int c = 0; c < 6; c++) {
            int g = tid + 256 * c;
            int row = g / 24, seg = g % 24;
            CP_ASYNC16(sb + row * (KSTR * 2) + seg * 16,
                       Kg + (size_t)(j0p + row) * 192 + seg * 8);
        }
#pragma unroll
        for (int c = 0; c < 2; c++) {
            int g = tid + 256 * c;
            int row = g >> 3, seg = g & 7;
            CP_ASYNC16(sb + 25600 + row * (VSTR * 2) + seg * 16,
                       Vhg + (size_t)row * TT + j0p + seg * 8);
            CP_ASYNC16(sb + 34816 + row * (VSTR * 2) + seg * 16,
                       Vlg + (size_t)row * TT + j0p + seg * 8);
        }
    };

    issue(0); CP_COMMIT();

    for (int jt = 0; jt < jmax; jt++) {
        if (jt + 1 < jmax) { issue(jt + 1); CP_COMMIT(); CP_WAIT1(); }
        else CP_WAIT0();
        __syncthreads();

        const int j0 = jt * 64;
        if (j0 <= q0 + wm * 16 + 15) {          // warp has unmasked work
            uint32_t sb = su + (jt & 1) * ATT_STG;

            // ---- S = Q K^T (n = kv cols 0..63)
            float sacc[8][4];
#pragma unroll
            for (int i = 0; i < 8; i++)
#pragma unroll
                for (int j = 0; j < 4; j++) sacc[i][j] = 0.f;

            uint32_t kb = sb + (lr + ((sel >> 1) << 3)) * (KSTR * 2)
                        + (((sel & 1) << 3)) * 2;
#pragma unroll
            for (int kk = 0; kk < 12; kk++) {
#pragma unroll
                for (int w = 0; w < 4; w++) {
                    uint32_t r4[4];
                    ldm_x4(r4, kb + (w * 16) * (KSTR * 2) + kk * 32);
                    mma16816(sacc[2 * w],     qf[kk], r4);
                    mma16816(sacc[2 * w + 1], qf[kk], r4 + 2);
                }
            }

            // ---- causal mask (diagonal region only)
            int r0 = q0 + wm * 16 + (lane >> 2);
            if (j0 + 63 > q0 + wm * 16) {
#pragma unroll
                for (int nt = 0; nt < 8; nt++) {
                    int cb = j0 + nt * 8 + (lane & 3) * 2;
                    if (cb     > r0)     sacc[nt][0] = -1e30f;
                    if (cb + 1 > r0)     sacc[nt][1] = -1e30f;
                    if (cb     > r0 + 8) sacc[nt][2] = -1e30f;
                    if (cb + 1 > r0 + 8) sacc[nt][3] = -1e30f;
                }
            }

            // ---- online softmax (base-2, poly exp on FMA pipe)
            float mx0 = -1e30f, mx1 = -1e30f;
#pragma unroll
            for (int nt = 0; nt < 8; nt++) {
                mx0 = fmaxf(mx0, fmaxf(sacc[nt][0], sacc[nt][1]));
                mx1 = fmaxf(mx1, fmaxf(sacc[nt][2], sacc[nt][3]));
            }
            mx0 = fmaxf(mx0, __shfl_xor_sync(0xffffffffu, mx0, 1));
            mx0 = fmaxf(mx0, __shfl_xor_sync(0xffffffffu, mx0, 2));
            mx1 = fmaxf(mx1, __shfl_xor_sync(0xffffffffu, mx1, 1));
            mx1 = fmaxf(mx1, __shfl_xor_sync(0xffffffffu, mx1, 2));
            float mn0 = fmaxf(mrow0, mx0), mn1 = fmaxf(mrow1, mx1);
            float a0 = exp2p(mrow0 - mn0), a1 = exp2p(mrow1 - mn1);
            mrow0 = mn0; mrow1 = mn1;
            lrow0 *= a0; lrow1 *= a1;
#pragma unroll
            for (int nt = 0; nt < 8; nt++) {
                oacc[nt][0] *= a0; oacc[nt][1] *= a0;
                oacc[nt][2] *= a1; oacc[nt][3] *= a1;
            }
            float rs0 = 0.f, rs1 = 0.f;
#pragma unroll
            for (int nt = 0; nt < 8; nt++) {
                sacc[nt][0] = exp2p(sacc[nt][0] - mn0);
                sacc[nt][1] = exp2p(sacc[nt][1] - mn0);
                sacc[nt][2] = exp2p(sacc[nt][2] - mn1);
                sacc[nt][3] = exp2p(sacc[nt][3] - mn1);
                rs0 += sacc[nt][0] + sacc[nt][1];
                rs1 += sacc[nt][2] + sacc[nt][3];
            }
            rs0 += __shfl_xor_sync(0xffffffffu, rs0, 1);
            rs0 += __shfl_xor_sync(0xffffffffu, rs0, 2);
            rs1 += __shfl_xor_sync(0xffffffffu, rs1, 1);
            rs1 += __shfl_xor_sync(0xffffffffu, rs1, 2);
            lrow0 += rs0; lrow1 += rs1;

            // ---- pack P hi (truncate) / lo into A-fragments
            uint32_t ah[4][4], al[4][4];
#pragma unroll
            for (int k2 = 0; k2 < 4; k2++) {
                float p00 = sacc[2 * k2][0],     p01 = sacc[2 * k2][1];
                float p02 = sacc[2 * k2][2],     p03 = sacc[2 * k2][3];
                float p10 = sacc[2 * k2 + 1][0], p11 = sacc[2 * k2 + 1][1];
                float p12 = sacc[2 * k2 + 1][2], p13 = sacc[2 * k2 + 1][3];
                ah[k2][0] = prmt_hi16(p00, p01);
                ah[k2][1] = prmt_hi16(p02, p03);
                ah[k2][2] = prmt_hi16(p10, p11);
                ah[k2][3] = prmt_hi16(p12, p13);
                al[k2][0] = pack_bf16(p00 - trunc_bf(p00), p01 - trunc_bf(p01));
                al[k2][1] = pack_bf16(p02 - trunc_bf(p02), p03 - trunc_bf(p03));
                al[k2][2] = pack_bf16(p10 - trunc_bf(p10), p11 - trunc_bf(p11));
                al[k2][3] = pack_bf16(p12 - trunc_bf(p12), p13 - trunc_bf(p13));
            }

            // ---- O += P V  (3-term: Ph*Vh + Pl*Vh + Ph*Vl), n = hd cols
            uint32_t vb = sb + 25600 + (lr + ((sel >> 1) << 3)) * (VSTR * 2)
                        + (((sel & 1) << 3)) * 2;
#pragma unroll
            for (int k2 = 0; k2 < 4; k2++) {
#pragma unroll
                for (int w = 0; w < 4; w++) {
                    uint32_t v4[4];
                    ldm_x4(v4, vb + (w * 16) * (VSTR * 2) + k2 * 32);
                    mma16816(oacc[2 * w],     ah[k2], v4);
                    mma16816(oacc[2 * w + 1], ah[k2], v4 + 2);
                    mma16816(oacc[2 * w],     al[k2], v4);
                    mma16816(oacc[2 * w + 1], al[k2], v4 + 2);
                    ldm_x4(v4, vb + 9216 + (w * 16) * (VSTR * 2) + k2 * 32);
                    mma16816(oacc[2 * w],     ah[k2], v4);
                    mma16816(oacc[2 * w + 1], ah[k2], v4 + 2);
                }
            }
        }
        __syncthreads();
    }

    // ---- epilogue: write hi/lo split A3 for out-projection directly
    float inv0 = 1.f / lrow0, inv1 = 1.f / lrow1;
    int b = bh >> 4, h = bh & 15;
    int r0 = q0 + wm * 16 + (lane >> 2);
#pragma unroll
    for (int nt = 0; nt < 8; nt++) {
        int col = h * HDIM + nt * 8 + (lane & 3) * 2;
#pragma unroll
        for (int half = 0; half < 2; half++) {
            float v0 = oacc[nt][2 * half]     * (half ? inv1 : inv0);
            float v1 = oacc[nt][2 * half + 1] * (half ? inv1 : inv0);
            float h0 = __bfloat162float(__float2bfloat16(v0));
            float h1 = __bfloat162float(__float2bfloat16(v1));
            uint32_t whi = pack_bf16(v0, v1);
            uint32_t wlo = pack_bf16(v0 - h0, v1 - h1);
            size_t rb = (size_t)(b * TT + r0 + half * 8) * K3;
            *(uint32_t*)((char*)(A3 + rb + col) )           = whi;
            *(uint32_t*)((char*)(A3 + rb + DD + col) )      = whi;
            *(uint32_t*)((char*)(A3 + rb + 2 * DD + col) )  = wlo;
        }
    }
}

// ---------------- launch -----------------------------------------------------
extern "C" void kernel_launch(void* const* d_in, const int* in_sizes, int n_in,
                              void* d_out, int out_size)
{
    const float* x     = (const float*)d_in[0];
    const float* qkv_w = (const float*)d_in[1];
    const float* qkv_b = (const float*)d_in[2];
    const float* out_w = (const float*)d_in[3];
    const float* out_b = (const float*)d_in[4];
    float* out = (float*)d_out;

    float *qkv;
    __nv_bfloat16 *a3, *bq3, *bo3, *q3, *k3, *vth, *vtl;
    cudaGetSymbolAddress((void**)&qkv, g_qkv);
    cudaGetSymbolAddress((void**)&a3,  g_a3);
    cudaGetSymbolAddress((void**)&bq3, g_bq3);
    cudaGetSymbolAddress((void**)&bo3, g_bo3);
    cudaGetSymbolAddress((void**)&q3,  g_q3);
    cudaGetSymbolAddress((void**)&k3,  g_k3);
    cudaGetSymbolAddress((void**)&vth, g_vth);
    cudaGetSymbolAddress((void**)&vtl, g_vtl);

    cudaFuncSetAttribute(attn_mma, cudaFuncAttributeMaxDynamicSharedMemorySize,
                         ATT_SMEM);
    cudaFuncSetAttribute(gemm_mma, cudaFuncAttributeMaxDynamicSharedMemorySize,
                         GEMM_SMEM_MMA);

    // 0) bf16 hi/lo splits of x and W_qkv^T
    split_a<<<(M_ROWS * DD) / 256, 256>>>(x, a3, M_ROWS * DD);
    {
        dim3 g(N_QKV / 32, DD / 32);
        split_bt<<<g, 256>>>(qkv_w, bq3, N_QKV);
    }
    // 1) QKV projection via mma.sync
    {
        dim3 grid(N_QKV / 128, M_ROWS / 128);
        gemm_mma<<<grid, 256, GEMM_SMEM_MMA>>>(a3, bq3, qkv_b, qkv, N_QKV);
    }
    // 2) RoPE + split Q/K ; V transpose + split
    rope_split2<<<(BB * TT * NH * 32) / 256, 256>>>(qkv, q3, k3);
    {
        dim3 g(TT / 32, HDIM / 32, BH);
        vsplit_t<<<g, 256>>>(qkv, vth, vtl);
    }
    // 3) mma.sync flash attention (writes split A3 directly)
    {
        dim3 grid(TT / 128, BH);
        attn_mma<<<grid, 256, ATT_SMEM>>>(q3, k3, vth, vtl, a3);
    }
    // 4) Output projection via mma.sync
    {
        dim3 g(DD / 32, DD / 32);
        split_bt<<<g, 256>>>(out_w, bo3, DD);
    }
    {
        dim3 grid(DD / 128, M_ROWS / 128);
        gemm_mma<<<grid, 256, GEMM_SMEM_MMA>>>(a3, bo3, out_b, out, DD);
    }
}